// round 8
// baseline (speedup 1.0000x reference)
#include <cuda_runtime.h>
#include <math.h>
#include <stdint.h>

#define THREADS 256
#define TT      64
#define N_TOK   65536
#define NCTA    (N_TOK / TT)     // 1024
#define DM      128
#define HID     256
#define NN      17
#define NF      32
#define ND      544              // 17*32

// padded smem strides (floats) — chosen so (stride mod 32) spreads banks
#define NSY  548                 // ns row stride    (4r+c bank spread)
#define XSY  132                 // staged-x stride
#define HBY  260                 // h row stride

#define OFF_NS   0
#define SZ_NS    (TT * NSY)            // 35072
#define OFF_HB   (OFF_NS + SZ_NS)      // 35072
#define SZ_HB    (TT * HBY)            // 16640
#define OFF_ADJ  (OFF_HB + SZ_HB)      // 51712
#define SZ_ADJ   292
#define SMEM_FLOATS (OFF_ADJ + SZ_ADJ) // 52004 floats = 208016 B

__device__ __forceinline__ float gelu_f(float v) {
    return 0.5f * v * (1.0f + erff(v * 0.7071067811865476f));
}

// round-to-nearest tf32 split: v ≈ hi + lo, each exactly representable in tf32
__device__ __forceinline__ void tf32_split(float v, uint32_t& hi, uint32_t& lo) {
    asm("cvt.rna.tf32.f32 %0, %1;" : "=r"(hi) : "f"(v));
    float r = v - __uint_as_float(hi);
    asm("cvt.rna.tf32.f32 %0, %1;" : "=r"(lo) : "f"(r));
}

// m16n8k8 tf32 MMA, fp32 accumulate (plain sm_80+ PTX — no sm_103a feature needed)
__device__ __forceinline__ void mma_tf32(float* d, const uint32_t* a, const uint32_t* b) {
    asm volatile(
        "mma.sync.aligned.m16n8k8.row.col.f32.tf32.tf32.f32 "
        "{%0,%1,%2,%3}, {%4,%5,%6,%7}, {%8,%9}, {%0,%1,%2,%3};"
        : "+f"(d[0]), "+f"(d[1]), "+f"(d[2]), "+f"(d[3])
        : "r"(a[0]), "r"(a[1]), "r"(a[2]), "r"(a[3]), "r"(b[0]), "r"(b[1]));
}

// ---------------- GAT layer (token-local, warp owns 8 tokens) ----------------
template<bool FINAL>
__device__ __forceinline__ void gat_layer(
    float* __restrict__ ns, float* __restrict__ buf, float* __restrict__ adjs,
    const float* __restrict__ adjG, const float* __restrict__ WgG,
    const float* __restrict__ bgG,
    const float* __restrict__ Wc, const float* __restrict__ bc,
    float* __restrict__ outp, int tid)
{
    const int lane = tid & 31;
    const int wid  = tid >> 5;

    if (tid < NN) {
        float r[NN];
        float mx = -3.0e38f;
        #pragma unroll
        for (int j = 0; j < NN; j++) { r[j] = adjG[tid * NN + j]; mx = fmaxf(mx, r[j]); }
        float s = 0.0f;
        #pragma unroll
        for (int j = 0; j < NN; j++) { r[j] = expf(r[j] - mx); s += r[j]; }
        float inv = 1.0f / s;
        #pragma unroll
        for (int j = 0; j < NN; j++) adjs[tid * NN + j] = r[j] * inv;
    }

    float wg[NF];
    #pragma unroll
    for (int g = 0; g < NF; g++) wg[g] = WgG[g * NF + lane];
    const float bgv = bgG[lane];
    float wc0 = 0.0f, wc1 = 0.0f, bc0 = 0.0f, bc1 = 0.0f;
    if (FINAL) { wc0 = Wc[2 * lane]; wc1 = Wc[2 * lane + 1]; bc0 = bc[0]; bc1 = bc[1]; }

    __syncthreads();   // adjs ready; also orders vs previous phase's buf use

    float* wb = buf + wid * (NN * 36);

    for (int tloc = 0; tloc < TT / 8; tloc++) {
        const int t = wid * (TT / 8) + tloc;
        const float* nt = ns + t * NSY;

        #pragma unroll 1
        for (int i = 0; i < NN; i++) {
            const float* ar = adjs + i * NN;
            float m = 0.0f;
            #pragma unroll
            for (int j = 0; j < NN; j++) m += ar[j] * nt[j * NF + lane];
            wb[i * 36 + lane] = m;
        }
        __syncwarp();

        #pragma unroll 1
        for (int i = 0; i < NN; i++) {
            float o = bgv;
            const float4* mp = reinterpret_cast<const float4*>(wb + i * 36);
            #pragma unroll
            for (int q = 0; q < 8; q++) {
                float4 mv = mp[q];
                o += mv.x * wg[4*q] + mv.y * wg[4*q+1] + mv.z * wg[4*q+2] + mv.w * wg[4*q+3];
            }
            const float val = gelu_f(o) + nt[i * NF + lane];
            if (FINAL) {
                float s0 = val * wc0;
                float s1 = val * wc1;
                #pragma unroll
                for (int off = 16; off; off >>= 1) {
                    s0 += __shfl_xor_sync(0xffffffffu, s0, off);
                    s1 += __shfl_xor_sync(0xffffffffu, s1, off);
                }
                if (lane == 0) {
                    float2 r2;
                    r2.x = s0 + bc0;
                    r2.y = s1 + bc1;
                    *reinterpret_cast<float2*>(outp + (t * NN + i) * 2) = r2;
                }
            } else {
                ns[t * NSY + i * NF + lane] = val;
            }
        }
        __syncwarp();
    }
    __syncthreads();
}

// ---------------- fused kernel ----------------
extern "C" __global__ void __launch_bounds__(THREADS, 1)
biogat_kernel(const float* __restrict__ x,
              const float* __restrict__ W1,  const float* __restrict__ b1,
              const float* __restrict__ W2,  const float* __restrict__ b2,
              const float* __restrict__ adj1, const float* __restrict__ Wg1, const float* __restrict__ bg1,
              const float* __restrict__ adj2, const float* __restrict__ Wg2, const float* __restrict__ bg2,
              const float* __restrict__ Wc,  const float* __restrict__ bc,
              float* __restrict__ out)
{
    extern __shared__ float sh[];
    float* ns   = sh + OFF_NS;    // stride NSY (phase2 out / GAT); rows 0.. also alias staged x
    float* hb   = sh + OFF_HB;    // stride HBY (phase1 out / phase2 A); aliases GAT wb later
    float* adjs = sh + OFF_ADJ;

    const int tid  = threadIdx.x;
    const int w    = tid >> 5;
    const int lane = tid & 31;
    const int g    = lane >> 2;   // fragment groupID
    const int tg   = lane & 3;    // thread-in-group
    const int tok0 = blockIdx.x * TT;

    // ---- stage x [64][128] into xs (= ns base, stride 132) ----
    {
        const float4* xg = reinterpret_cast<const float4*>(x + (size_t)tok0 * DM);
        for (int i = tid; i < TT * 32; i += THREADS) {
            int r = i >> 5, c4 = (i & 31) << 2;
            float4 v = xg[i];
            *reinterpret_cast<float4*>(ns + r * XSY + c4) = v;
        }
    }
    __syncthreads();

    // ================= phase 1: h = gelu(x @ W1 + b1)  (tf32x3 MMA) =================
    #pragma unroll 1
    for (int pp = 0; pp < 2; pp++) {
        const int n0 = 16 * (w + 8 * pp);       // 16-col pair
        float d[4][2][4] = {};
        #pragma unroll 1
        for (int ks = 0; ks < 16; ks++) {
            const int k0 = ks * 8;
            uint32_t ah[4][4], al[4][4];
            #pragma unroll
            for (int mi = 0; mi < 4; mi++) {
                const float* ap = ns + (16 * mi + g) * XSY + k0 + tg;
                tf32_split(ap[0],          ah[mi][0], al[mi][0]);
                tf32_split(ap[8 * XSY],    ah[mi][1], al[mi][1]);
                tf32_split(ap[4],          ah[mi][2], al[mi][2]);
                tf32_split(ap[8 * XSY + 4],ah[mi][3], al[mi][3]);
            }
            uint32_t bh[2][2], bl[2][2];
            #pragma unroll
            for (int fi = 0; fi < 2; fi++) {
                const float* bp = W1 + (k0 + tg) * HID + n0 + 8 * fi + g;
                tf32_split(bp[0],       bh[fi][0], bl[fi][0]);
                tf32_split(bp[4 * HID], bh[fi][1], bl[fi][1]);
            }
            #pragma unroll
            for (int mi = 0; mi < 4; mi++)
                #pragma unroll
                for (int fi = 0; fi < 2; fi++) {
                    mma_tf32(d[mi][fi], ah[mi], bh[fi]);
                    mma_tf32(d[mi][fi], al[mi], bh[fi]);
                    mma_tf32(d[mi][fi], ah[mi], bl[fi]);
                }
        }
        #pragma unroll
        for (int mi = 0; mi < 4; mi++)
            #pragma unroll
            for (int fi = 0; fi < 2; fi++) {
                const int c0 = n0 + 8 * fi + 2 * tg;
                const float2 bv = *reinterpret_cast<const float2*>(b1 + c0);
                const int r0 = 16 * mi + g;
                float2 o0, o1;
                o0.x = gelu_f(d[mi][fi][0] + bv.x);
                o0.y = gelu_f(d[mi][fi][1] + bv.y);
                o1.x = gelu_f(d[mi][fi][2] + bv.x);
                o1.y = gelu_f(d[mi][fi][3] + bv.y);
                *reinterpret_cast<float2*>(hb + r0 * HBY + c0)       = o0;
                *reinterpret_cast<float2*>(hb + (r0 + 8) * HBY + c0) = o1;
            }
    }
    __syncthreads();

    // ================= phase 2: nodes = h @ W2 + b2  (tf32x3 MMA) =================
    #pragma unroll 1
    for (int j = 0; j < 5; j++) {
        const int p = w + 8 * j;                // 34 col-pairs over 544 cols
        if (p >= 34) break;
        const int n0 = 16 * p;
        float d[4][2][4] = {};
        #pragma unroll 1
        for (int ks = 0; ks < 32; ks++) {
            const int k0 = ks * 8;
            uint32_t ah[4][4], al[4][4];
            #pragma unroll
            for (int mi = 0; mi < 4; mi++) {
                const float* ap = hb + (16 * mi + g) * HBY + k0 + tg;
                tf32_split(ap[0],          ah[mi][0], al[mi][0]);
                tf32_split(ap[8 * HBY],    ah[mi][1], al[mi][1]);
                tf32_split(ap[4],          ah[mi][2], al[mi][2]);
                tf32_split(ap[8 * HBY + 4],ah[mi][3], al[mi][3]);
            }
            uint32_t bh[2][2], bl[2][2];
            #pragma unroll
            for (int fi = 0; fi < 2; fi++) {
                const float* bp = W2 + (k0 + tg) * ND + n0 + 8 * fi + g;
                tf32_split(bp[0],      bh[fi][0], bl[fi][0]);
                tf32_split(bp[4 * ND], bh[fi][1], bl[fi][1]);
            }
            #pragma unroll
            for (int mi = 0; mi < 4; mi++)
                #pragma unroll
                for (int fi = 0; fi < 2; fi++) {
                    mma_tf32(d[mi][fi], ah[mi], bh[fi]);
                    mma_tf32(d[mi][fi], al[mi], bh[fi]);
                    mma_tf32(d[mi][fi], ah[mi], bl[fi]);
                }
        }
        #pragma unroll
        for (int mi = 0; mi < 4; mi++)
            #pragma unroll
            for (int fi = 0; fi < 2; fi++) {
                const int c0 = n0 + 8 * fi + 2 * tg;
                const float2 bv = *reinterpret_cast<const float2*>(b2 + c0);
                const int r0 = 16 * mi + g;
                float2 o0, o1;
                o0.x = d[mi][fi][0] + bv.x;
                o0.y = d[mi][fi][1] + bv.y;
                o1.x = d[mi][fi][2] + bv.x;
                o1.y = d[mi][fi][3] + bv.y;
                *reinterpret_cast<float2*>(ns + r0 * NSY + c0)       = o0;
                *reinterpret_cast<float2*>(ns + (r0 + 8) * NSY + c0) = o1;
            }
    }
    __syncthreads();

    // ================= GAT1, GAT2 (+fused coord projection) =================
    gat_layer<false>(ns, hb, adjs, adj1, Wg1, bg1, Wc, bc, nullptr, tid);
    gat_layer<true >(ns, hb, adjs, adj2, Wg2, bg2, Wc, bc,
                     out + (size_t)tok0 * NN * 2, tid);
}

extern "C" void kernel_launch(void* const* d_in, const int* in_sizes, int n_in,
                              void* d_out, int out_size) {
    const float* x    = (const float*)d_in[0];
    const float* W1   = (const float*)d_in[1];
    const float* b1   = (const float*)d_in[2];
    const float* W2   = (const float*)d_in[3];
    const float* b2   = (const float*)d_in[4];
    const float* adj1 = (const float*)d_in[5];
    const float* Wg1  = (const float*)d_in[6];
    const float* bg1  = (const float*)d_in[7];
    const float* adj2 = (const float*)d_in[8];
    const float* Wg2  = (const float*)d_in[9];
    const float* bg2  = (const float*)d_in[10];
    const float* Wc   = (const float*)d_in[11];
    const float* bc   = (const float*)d_in[12];
    float* out = (float*)d_out;

    const size_t smem = SMEM_FLOATS * sizeof(float);
    cudaFuncSetAttribute((const void*)biogat_kernel,
                         cudaFuncAttributeMaxDynamicSharedMemorySize, (int)smem);
    biogat_kernel<<<NCTA, THREADS, smem>>>(x, W1, b1, W2, b2,
                                           adj1, Wg1, bg1,
                                           adj2, Wg2, bg2,
                                           Wc, bc, out);
}

// round 11
// speedup vs baseline: 1.4711x; 1.4711x over previous
#include <cuda_runtime.h>
#include <math.h>
#include <stdint.h>

#define THREADS 512
#define TT      64
#define N_TOK   65536
#define NCTA    (N_TOK / TT)     // 1024
#define DM      128
#define HID     256
#define NN      17
#define NF      32
#define ND      544              // 17*32

#define NSY  548                 // ns row stride (floats)
#define HPLW 132                 // h-plane row stride (u32 words)

#define OFF_NS   0
#define SZ_NS    (TT * NSY)            // 35072 floats
#define OFF_HH   (OFF_NS + SZ_NS)      // hi plane: 64*132 u32
#define OFF_HL   (OFF_HH + TT * HPLW)  // lo plane
#define OFF_ADJ  (OFF_HL + TT * HPLW)  // 51968
#define SZ_ADJ   292
#define SMEM_FLOATS (OFF_ADJ + SZ_ADJ) // 52260 floats = 209040 B

__device__ __forceinline__ float gelu_f(float v) {
    return 0.5f * v * (1.0f + erff(v * 0.7071067811865476f));
}

// split a k-pair (v0 = even k, v1 = odd k) into packed bf16x2 hi and lo words.
// low half of word = v0 (even k), matching mma fragment element order.
__device__ __forceinline__ void pair_split(float v0, float v1, uint32_t& hi, uint32_t& lo) {
    uint32_t h;
    asm("cvt.rn.bf16x2.f32 %0, %1, %2;" : "=r"(h) : "f"(v1), "f"(v0));
    float h0 = __uint_as_float(h << 16);
    float h1 = __uint_as_float(h & 0xffff0000u);
    asm("cvt.rn.bf16x2.f32 %0, %1, %2;" : "=r"(lo) : "f"(v1 - h1), "f"(v0 - h0));
    hi = h;
}

// m16n8k16 bf16 MMA, fp32 accumulate (plain sm_80+ PTX, no sm_103a-only features)
__device__ __forceinline__ void mma_bf16(float* d, const uint32_t* a, const uint32_t* b) {
    asm volatile(
        "mma.sync.aligned.m16n8k16.row.col.f32.bf16.bf16.f32 "
        "{%0,%1,%2,%3}, {%4,%5,%6,%7}, {%8,%9}, {%0,%1,%2,%3};"
        : "+f"(d[0]), "+f"(d[1]), "+f"(d[2]), "+f"(d[3])
        : "r"(a[0]), "r"(a[1]), "r"(a[2]), "r"(a[3]), "r"(b[0]), "r"(b[1]));
}

// ---------------- GAT layer: 16 warps, warp owns 4 tokens ----------------
template<bool FINAL>
__device__ __forceinline__ void gat_layer(
    float* __restrict__ ns, float* __restrict__ buf, float* __restrict__ adjs,
    const float* __restrict__ adjG, const float* __restrict__ WgG,
    const float* __restrict__ bgG,
    const float* __restrict__ Wc, const float* __restrict__ bc,
    float* __restrict__ outp, int tid)
{
    const int lane = tid & 31;
    const int wid  = tid >> 5;

    if (tid < NN) {
        float r[NN];
        float mx = -3.0e38f;
        #pragma unroll
        for (int j = 0; j < NN; j++) { r[j] = adjG[tid * NN + j]; mx = fmaxf(mx, r[j]); }
        float s = 0.0f;
        #pragma unroll
        for (int j = 0; j < NN; j++) { r[j] = expf(r[j] - mx); s += r[j]; }
        float inv = 1.0f / s;
        #pragma unroll
        for (int j = 0; j < NN; j++) adjs[tid * NN + j] = r[j] * inv;
    }

    float wg[NF];
    #pragma unroll
    for (int g = 0; g < NF; g++) wg[g] = WgG[g * NF + lane];
    const float bgv = bgG[lane];
    float wc0 = 0.0f, wc1 = 0.0f, bc0 = 0.0f, bc1 = 0.0f;
    if (FINAL) { wc0 = Wc[2 * lane]; wc1 = Wc[2 * lane + 1]; bc0 = bc[0]; bc1 = bc[1]; }

    __syncthreads();   // adjs ready; orders vs previous phase

    float* wb = buf + wid * (NN * 36);

    for (int tloc = 0; tloc < 4; tloc++) {
        const int t = wid * 4 + tloc;
        const float* nt = ns + t * NSY;

        #pragma unroll 1
        for (int i = 0; i < NN; i++) {
            const float* ar = adjs + i * NN;
            float m = 0.0f;
            #pragma unroll
            for (int j = 0; j < NN; j++) m += ar[j] * nt[j * NF + lane];
            wb[i * 36 + lane] = m;
        }
        __syncwarp();

        #pragma unroll 1
        for (int i = 0; i < NN; i++) {
            float o = bgv;
            const float4* mp = reinterpret_cast<const float4*>(wb + i * 36);
            #pragma unroll
            for (int q = 0; q < 8; q++) {
                float4 mv = mp[q];
                o += mv.x * wg[4*q] + mv.y * wg[4*q+1] + mv.z * wg[4*q+2] + mv.w * wg[4*q+3];
            }
            const float val = gelu_f(o) + nt[i * NF + lane];
            if (FINAL) {
                float s0 = val * wc0;
                float s1 = val * wc1;
                #pragma unroll
                for (int off = 16; off; off >>= 1) {
                    s0 += __shfl_xor_sync(0xffffffffu, s0, off);
                    s1 += __shfl_xor_sync(0xffffffffu, s1, off);
                }
                if (lane == 0) {
                    float2 r2;
                    r2.x = s0 + bc0;
                    r2.y = s1 + bc1;
                    *reinterpret_cast<float2*>(outp + (t * NN + i) * 2) = r2;
                }
            } else {
                ns[t * NSY + i * NF + lane] = val;
            }
        }
        __syncwarp();
    }
    __syncthreads();
}

// ---------------- fused kernel ----------------
extern "C" __global__ void __launch_bounds__(THREADS, 1)
biogat_kernel(const float* __restrict__ x,
              const float* __restrict__ W1,  const float* __restrict__ b1,
              const float* __restrict__ W2,  const float* __restrict__ b2,
              const float* __restrict__ adj1, const float* __restrict__ Wg1, const float* __restrict__ bg1,
              const float* __restrict__ adj2, const float* __restrict__ Wg2, const float* __restrict__ bg2,
              const float* __restrict__ Wc,  const float* __restrict__ bc,
              float* __restrict__ out)
{
    extern __shared__ float sh[];
    float*    ns   = sh + OFF_NS;
    uint32_t* hh   = reinterpret_cast<uint32_t*>(sh + OFF_HH);
    uint32_t* hl   = reinterpret_cast<uint32_t*>(sh + OFF_HL);
    float*    adjs = sh + OFF_ADJ;

    const int tid  = threadIdx.x;
    const int w    = tid >> 5;    // 0..15
    const int lane = tid & 31;
    const int g    = lane >> 2;   // groupID 0..7
    const int tg   = lane & 3;    // thread-in-group
    const int tok0 = blockIdx.x * TT;

    // ================= phase 1: h = gelu(x @ W1 + b1) =================
    // warp w computes cols 16w..16w+15 (= k-chunk w of h), all 64 rows, bf16x3.
    {
        const int n0 = 16 * w;
        float d[4][2][4] = {};
        #pragma unroll 1
        for (int kc = 0; kc < 8; kc++) {
            const int k0 = kc * 16 + 2 * tg;
            uint32_t bh[2][2], bl[2][2];
            #pragma unroll
            for (int fi = 0; fi < 2; fi++) {
                const float* bp = W1 + k0 * HID + n0 + 8 * fi + g;
                pair_split(bp[0],       bp[HID],     bh[fi][0], bl[fi][0]);
                pair_split(bp[8 * HID], bp[9 * HID], bh[fi][1], bl[fi][1]);
            }
            #pragma unroll
            for (int mi = 0; mi < 4; mi++) {
                const float* ap = x + (size_t)(tok0 + 16 * mi + g) * DM + k0;
                uint32_t ah[4], al[4];
                float2 v;
                v = *reinterpret_cast<const float2*>(ap);              pair_split(v.x, v.y, ah[0], al[0]);
                v = *reinterpret_cast<const float2*>(ap + 8 * DM);     pair_split(v.x, v.y, ah[1], al[1]);
                v = *reinterpret_cast<const float2*>(ap + 8);          pair_split(v.x, v.y, ah[2], al[2]);
                v = *reinterpret_cast<const float2*>(ap + 8 * DM + 8); pair_split(v.x, v.y, ah[3], al[3]);
                #pragma unroll
                for (int fi = 0; fi < 2; fi++) {
                    mma_bf16(d[mi][fi], ah, bh[fi]);
                    mma_bf16(d[mi][fi], al, bh[fi]);
                    mma_bf16(d[mi][fi], ah, bl[fi]);
                }
            }
        }
        // epilogue: bias + gelu + split-pack into h planes.
        // col c = n0+8fi+2tg(+1) -> k-chunk w, k-pair 4fi+tg -> slot 2tg+fi.
        const float2 bv0 = *reinterpret_cast<const float2*>(b1 + n0 + 2 * tg);
        const float2 bv1 = *reinterpret_cast<const float2*>(b1 + n0 + 8 + 2 * tg);
        #pragma unroll
        for (int mi = 0; mi < 4; mi++) {
            #pragma unroll
            for (int half = 0; half < 2; half++) {
                const int row = 16 * mi + g + 8 * half;
                uint32_t hw0, lw0, hw1, lw1;
                pair_split(gelu_f(d[mi][0][2*half]   + bv0.x),
                           gelu_f(d[mi][0][2*half+1] + bv0.y), hw0, lw0);
                pair_split(gelu_f(d[mi][1][2*half]   + bv1.x),
                           gelu_f(d[mi][1][2*half+1] + bv1.y), hw1, lw1);
                const int widx = row * HPLW + w * 8 + 2 * tg;
                uint2 hv; hv.x = hw0; hv.y = hw1;
                uint2 lv; lv.x = lw0; lv.y = lw1;
                *reinterpret_cast<uint2*>(hh + widx) = hv;
                *reinterpret_cast<uint2*>(hl + widx) = lv;
            }
        }
    }
    __syncthreads();

    // ================= phase 2: nodes = h @ W2 + b2 =================
    // 34 jobs of 16 cols; warp w does j = w, w+16 (and w+32 for w<2).
    #pragma unroll 1
    for (int j = w; j < 34; j += 16) {
        const int n0 = 16 * j;
        float d[4][2][4] = {};
        #pragma unroll 1
        for (int kc = 0; kc < 16; kc++) {
            const int k0 = kc * 16 + 2 * tg;
            uint32_t bh[2][2], bl[2][2];
            #pragma unroll
            for (int nf = 0; nf < 2; nf++) {
                const float* bp = W2 + (size_t)k0 * ND + n0 + 8 * nf + g;
                pair_split(bp[0],      bp[ND],     bh[nf][0], bl[nf][0]);
                pair_split(bp[8 * ND], bp[9 * ND], bh[nf][1], bl[nf][1]);
            }
            #pragma unroll
            for (int mi = 0; mi < 4; mi++) {
                const int r0 = 16 * mi + g;
                const int base = kc * 8 + 2 * tg;
                uint32_t ah[4], al[4];
                uint2 t0, t1;
                t0 = *reinterpret_cast<const uint2*>(hh + r0 * HPLW + base);
                t1 = *reinterpret_cast<const uint2*>(hh + (r0 + 8) * HPLW + base);
                ah[0] = t0.x; ah[2] = t0.y; ah[1] = t1.x; ah[3] = t1.y;
                t0 = *reinterpret_cast<const uint2*>(hl + r0 * HPLW + base);
                t1 = *reinterpret_cast<const uint2*>(hl + (r0 + 8) * HPLW + base);
                al[0] = t0.x; al[2] = t0.y; al[1] = t1.x; al[3] = t1.y;
                #pragma unroll
                for (int nf = 0; nf < 2; nf++) {
                    mma_bf16(d[mi][nf], ah, bh[nf]);
                    mma_bf16(d[mi][nf], al, bh[nf]);
                    mma_bf16(d[mi][nf], ah, bl[nf]);
                }
            }
        }
        // epilogue: bias + fp32 store to ns
        #pragma unroll
        for (int nf = 0; nf < 2; nf++) {
            const int c0 = n0 + 8 * nf + 2 * tg;
            const float2 bv = *reinterpret_cast<const float2*>(b2 + c0);
            #pragma unroll
            for (int mi = 0; mi < 4; mi++) {
                const int r0 = 16 * mi + g;
                float2 o0, o1;
                o0.x = d[mi][nf][0] + bv.x;
                o0.y = d[mi][nf][1] + bv.y;
                o1.x = d[mi][nf][2] + bv.x;
                o1.y = d[mi][nf][3] + bv.y;
                *reinterpret_cast<float2*>(ns + r0 * NSY + c0)       = o0;
                *reinterpret_cast<float2*>(ns + (r0 + 8) * NSY + c0) = o1;
            }
        }
    }
    __syncthreads();

    // ================= GAT1, GAT2 (+fused coord projection) =================
    // wb aliases the (now dead) h planes: 16 warps * 612 floats = 9792 <= 16896.
    float* wb = reinterpret_cast<float*>(hh);
    gat_layer<false>(ns, wb, adjs, adj1, Wg1, bg1, Wc, bc, nullptr, tid);
    gat_layer<true >(ns, wb, adjs, adj2, Wg2, bg2, Wc, bc,
                     out + (size_t)tok0 * NN * 2, tid);
}

extern "C" void kernel_launch(void* const* d_in, const int* in_sizes, int n_in,
                              void* d_out, int out_size) {
    const float* x    = (const float*)d_in[0];
    const float* W1   = (const float*)d_in[1];
    const float* b1   = (const float*)d_in[2];
    const float* W2   = (const float*)d_in[3];
    const float* b2   = (const float*)d_in[4];
    const float* adj1 = (const float*)d_in[5];
    const float* Wg1  = (const float*)d_in[6];
    const float* bg1  = (const float*)d_in[7];
    const float* adj2 = (const float*)d_in[8];
    const float* Wg2  = (const float*)d_in[9];
    const float* bg2  = (const float*)d_in[10];
    const float* Wc   = (const float*)d_in[11];
    const float* bc   = (const float*)d_in[12];
    float* out = (float*)d_out;

    const size_t smem = SMEM_FLOATS * sizeof(float);
    cudaFuncSetAttribute((const void*)biogat_kernel,
                         cudaFuncAttributeMaxDynamicSharedMemorySize, (int)smem);
    biogat_kernel<<<NCTA, THREADS, smem>>>(x, W1, b1, W2, b2,
                                           adj1, Wg1, bg1,
                                           adj2, Wg2, bg2,
                                           Wc, bc, out);
}

// round 12
// speedup vs baseline: 1.5015x; 1.0206x over previous
#include <cuda_runtime.h>
#include <math.h>
#include <stdint.h>

#define THREADS 512
#define TT      64
#define N_TOK   65536
#define NCTA    (N_TOK / TT)     // 1024
#define DM      128
#define HID     256
#define NN      17
#define NF      32
#define ND      544              // 17*32

#define NSY  548                 // ns row stride (floats)
#define HPLW 132                 // h-plane row stride (u32 words)
#define XPW  68                  // x-plane row stride (u32 words)

#define OFF_NS   0
#define SZ_NS    (TT * NSY)            // 35072 floats
#define OFF_HH   (OFF_NS + SZ_NS)      // hi plane: 64*132 u32
#define OFF_HL   (OFF_HH + TT * HPLW)  // lo plane
#define OFF_ADJ  (OFF_HL + TT * HPLW)  // 51968
#define SZ_ADJ   292
#define SMEM_FLOATS (OFF_ADJ + SZ_ADJ) // 52260 floats = 209040 B

__device__ __forceinline__ float gelu_f(float v) {
    return 0.5f * v * (1.0f + erff(v * 0.7071067811865476f));
}

// split a k-pair (v0 = even k, v1 = odd k) into packed bf16x2 hi and lo words.
// low half of word = v0 (even k), matching mma fragment element order.
__device__ __forceinline__ void pair_split(float v0, float v1, uint32_t& hi, uint32_t& lo) {
    uint32_t h;
    asm("cvt.rn.bf16x2.f32 %0, %1, %2;" : "=r"(h) : "f"(v1), "f"(v0));
    float h0 = __uint_as_float(h << 16);
    float h1 = __uint_as_float(h & 0xffff0000u);
    asm("cvt.rn.bf16x2.f32 %0, %1, %2;" : "=r"(lo) : "f"(v1 - h1), "f"(v0 - h0));
    hi = h;
}

// m16n8k16 bf16 MMA, fp32 accumulate (plain sm_80+ PTX, no sm_103a-only features)
__device__ __forceinline__ void mma_bf16(float* d, const uint32_t* a, const uint32_t* b) {
    asm volatile(
        "mma.sync.aligned.m16n8k16.row.col.f32.bf16.bf16.f32 "
        "{%0,%1,%2,%3}, {%4,%5,%6,%7}, {%8,%9}, {%0,%1,%2,%3};"
        : "+f"(d[0]), "+f"(d[1]), "+f"(d[2]), "+f"(d[3])
        : "r"(a[0]), "r"(a[1]), "r"(a[2]), "r"(a[3]), "r"(b[0]), "r"(b[1]));
}

// ---------------- GAT layer: 16 warps, warp owns 4 tokens ----------------
template<bool FINAL>
__device__ __forceinline__ void gat_layer(
    float* __restrict__ ns, float* __restrict__ buf, float* __restrict__ adjs,
    const float* __restrict__ adjG, const float* __restrict__ WgG,
    const float* __restrict__ bgG,
    const float* __restrict__ Wc, const float* __restrict__ bc,
    float* __restrict__ outp, int tid)
{
    const int lane = tid & 31;
    const int wid  = tid >> 5;

    if (tid < NN) {
        float r[NN];
        float mx = -3.0e38f;
        #pragma unroll
        for (int j = 0; j < NN; j++) { r[j] = adjG[tid * NN + j]; mx = fmaxf(mx, r[j]); }
        float s = 0.0f;
        #pragma unroll
        for (int j = 0; j < NN; j++) { r[j] = expf(r[j] - mx); s += r[j]; }
        float inv = 1.0f / s;
        #pragma unroll
        for (int j = 0; j < NN; j++) adjs[tid * NN + j] = r[j] * inv;
    }

    float wg[NF];
    #pragma unroll
    for (int g = 0; g < NF; g++) wg[g] = WgG[g * NF + lane];
    const float bgv = bgG[lane];
    float wc0 = 0.0f, wc1 = 0.0f, bc0 = 0.0f, bc1 = 0.0f;
    if (FINAL) { wc0 = Wc[2 * lane]; wc1 = Wc[2 * lane + 1]; bc0 = bc[0]; bc1 = bc[1]; }

    __syncthreads();   // adjs ready; orders vs previous phase

    float* wb = buf + wid * (NN * 36);

    for (int tloc = 0; tloc < 4; tloc++) {
        const int t = wid * 4 + tloc;
        const float* nt = ns + t * NSY;

        // register-cache this token's node features: 17 wide LDS instead of 306
        float nr[NN];
        #pragma unroll
        for (int j = 0; j < NN; j++) nr[j] = nt[j * NF + lane];

        #pragma unroll 1
        for (int i = 0; i < NN; i++) {
            const float* ar = adjs + i * NN;   // uniform broadcasts (cheap wavefronts)
            float m = 0.0f;
            #pragma unroll
            for (int j = 0; j < NN; j++) m += ar[j] * nr[j];
            wb[i * 36 + lane] = m;
        }
        __syncwarp();

        #pragma unroll 1
        for (int i = 0; i < NN; i++) {
            float o = bgv;
            const float4* mp = reinterpret_cast<const float4*>(wb + i * 36);
            #pragma unroll
            for (int q = 0; q < 8; q++) {
                float4 mv = mp[q];
                o += mv.x * wg[4*q] + mv.y * wg[4*q+1] + mv.z * wg[4*q+2] + mv.w * wg[4*q+3];
            }
            const float val = gelu_f(o) + nr[i];
            if (FINAL) {
                float s0 = val * wc0;
                float s1 = val * wc1;
                #pragma unroll
                for (int off = 16; off; off >>= 1) {
                    s0 += __shfl_xor_sync(0xffffffffu, s0, off);
                    s1 += __shfl_xor_sync(0xffffffffu, s1, off);
                }
                if (lane == 0) {
                    float2 r2;
                    r2.x = s0 + bc0;
                    r2.y = s1 + bc1;
                    *reinterpret_cast<float2*>(outp + (t * NN + i) * 2) = r2;
                }
            } else {
                ns[t * NSY + i * NF + lane] = val;
            }
        }
        __syncwarp();
    }
    __syncthreads();
}

// ---------------- fused kernel ----------------
extern "C" __global__ void __launch_bounds__(THREADS, 1)
biogat_kernel(const float* __restrict__ x,
              const float* __restrict__ W1,  const float* __restrict__ b1,
              const float* __restrict__ W2,  const float* __restrict__ b2,
              const float* __restrict__ adj1, const float* __restrict__ Wg1, const float* __restrict__ bg1,
              const float* __restrict__ adj2, const float* __restrict__ Wg2, const float* __restrict__ bg2,
              const float* __restrict__ Wc,  const float* __restrict__ bc,
              float* __restrict__ out)
{
    extern __shared__ float sh[];
    float*    ns   = sh + OFF_NS;
    uint32_t* hh   = reinterpret_cast<uint32_t*>(sh + OFF_HH);
    uint32_t* hl   = reinterpret_cast<uint32_t*>(sh + OFF_HL);
    float*    adjs = sh + OFF_ADJ;

    // x planes alias the ns region (ns is first written in phase 2, after all
    // phase-1 reads of the x planes have completed at the intervening barrier)
    uint32_t* xh = reinterpret_cast<uint32_t*>(sh + OFF_NS);
    uint32_t* xl = xh + TT * XPW;

    const int tid  = threadIdx.x;
    const int w    = tid >> 5;    // 0..15
    const int lane = tid & 31;
    const int g    = lane >> 2;   // groupID 0..7
    const int tg   = lane & 3;    // thread-in-group
    const int tok0 = blockIdx.x * TT;

    // ---- stage + split x ONCE into fragment-permuted bf16 hi/lo planes ----
    // pair q of row r -> chunk c=q>>3, pc=q&7 -> slot c*8 + 2*(pc&3) + (pc>>2)
    {
        const float2* xg = reinterpret_cast<const float2*>(x + (size_t)tok0 * DM);
        #pragma unroll
        for (int it = 0; it < (TT * 64) / THREADS; it++) {
            const int p = tid + it * THREADS;
            const int r = p >> 6, q = p & 63;
            float2 v = xg[p];
            uint32_t hi, lo; pair_split(v.x, v.y, hi, lo);
            const int slot = (q >> 3) * 8 + 2 * (q & 3) + ((q & 7) >> 2);
            xh[r * XPW + slot] = hi;
            xl[r * XPW + slot] = lo;
        }
    }
    __syncthreads();

    // ================= phase 1: h = gelu(x @ W1 + b1) =================
    // warp w computes cols 16w..16w+15 (= k-chunk w of h), all 64 rows, bf16x3.
    {
        const int n0 = 16 * w;
        float d[4][2][4] = {};
        #pragma unroll 1
        for (int kc = 0; kc < 8; kc++) {
            const int k0 = kc * 16 + 2 * tg;
            uint32_t bh[2][2], bl[2][2];
            #pragma unroll
            for (int fi = 0; fi < 2; fi++) {
                const float* bp = W1 + k0 * HID + n0 + 8 * fi + g;
                pair_split(bp[0],       bp[HID],     bh[fi][0], bl[fi][0]);
                pair_split(bp[8 * HID], bp[9 * HID], bh[fi][1], bl[fi][1]);
            }
            #pragma unroll
            for (int mi = 0; mi < 4; mi++) {
                const int r0 = 16 * mi + g;
                const int base = kc * 8 + 2 * tg;
                uint32_t ah[4], al[4];
                uint2 t0, t1;
                t0 = *reinterpret_cast<const uint2*>(xh + r0 * XPW + base);
                t1 = *reinterpret_cast<const uint2*>(xh + (r0 + 8) * XPW + base);
                ah[0] = t0.x; ah[2] = t0.y; ah[1] = t1.x; ah[3] = t1.y;
                t0 = *reinterpret_cast<const uint2*>(xl + r0 * XPW + base);
                t1 = *reinterpret_cast<const uint2*>(xl + (r0 + 8) * XPW + base);
                al[0] = t0.x; al[2] = t0.y; al[1] = t1.x; al[3] = t1.y;
                #pragma unroll
                for (int fi = 0; fi < 2; fi++) {
                    mma_bf16(d[mi][fi], ah, bh[fi]);
                    mma_bf16(d[mi][fi], al, bh[fi]);
                    mma_bf16(d[mi][fi], ah, bl[fi]);
                }
            }
        }
        // epilogue: bias + gelu + split-pack into h planes.
        const float2 bv0 = *reinterpret_cast<const float2*>(b1 + n0 + 2 * tg);
        const float2 bv1 = *reinterpret_cast<const float2*>(b1 + n0 + 8 + 2 * tg);
        #pragma unroll
        for (int mi = 0; mi < 4; mi++) {
            #pragma unroll
            for (int half = 0; half < 2; half++) {
                const int row = 16 * mi + g + 8 * half;
                uint32_t hw0, lw0, hw1, lw1;
                pair_split(gelu_f(d[mi][0][2*half]   + bv0.x),
                           gelu_f(d[mi][0][2*half+1] + bv0.y), hw0, lw0);
                pair_split(gelu_f(d[mi][1][2*half]   + bv1.x),
                           gelu_f(d[mi][1][2*half+1] + bv1.y), hw1, lw1);
                const int widx = row * HPLW + w * 8 + 2 * tg;
                uint2 hv; hv.x = hw0; hv.y = hw1;
                uint2 lv; lv.x = lw0; lv.y = lw1;
                *reinterpret_cast<uint2*>(hh + widx) = hv;
                *reinterpret_cast<uint2*>(hl + widx) = lv;
            }
        }
    }
    __syncthreads();

    // ================= phase 2: nodes = h @ W2 + b2 =================
    // 34 jobs of 16 cols; warp w does j = w, w+16 (and w+32 for w<2).
    #pragma unroll 1
    for (int j = w; j < 34; j += 16) {
        const int n0 = 16 * j;
        float d[4][2][4] = {};
        #pragma unroll 1
        for (int kc = 0; kc < 16; kc++) {
            const int k0 = kc * 16 + 2 * tg;
            uint32_t bh[2][2], bl[2][2];
            #pragma unroll
            for (int nf = 0; nf < 2; nf++) {
                const float* bp = W2 + (size_t)k0 * ND + n0 + 8 * nf + g;
                pair_split(bp[0],      bp[ND],     bh[nf][0], bl[nf][0]);
                pair_split(bp[8 * ND], bp[9 * ND], bh[nf][1], bl[nf][1]);
            }
            #pragma unroll
            for (int mi = 0; mi < 4; mi++) {
                const int r0 = 16 * mi + g;
                const int base = kc * 8 + 2 * tg;
                uint32_t ah[4], al[4];
                uint2 t0, t1;
                t0 = *reinterpret_cast<const uint2*>(hh + r0 * HPLW + base);
                t1 = *reinterpret_cast<const uint2*>(hh + (r0 + 8) * HPLW + base);
                ah[0] = t0.x; ah[2] = t0.y; ah[1] = t1.x; ah[3] = t1.y;
                t0 = *reinterpret_cast<const uint2*>(hl + r0 * HPLW + base);
                t1 = *reinterpret_cast<const uint2*>(hl + (r0 + 8) * HPLW + base);
                al[0] = t0.x; al[2] = t0.y; al[1] = t1.x; al[3] = t1.y;
                #pragma unroll
                for (int nf = 0; nf < 2; nf++) {
                    mma_bf16(d[mi][nf], ah, bh[nf]);
                    mma_bf16(d[mi][nf], al, bh[nf]);
                    mma_bf16(d[mi][nf], ah, bl[nf]);
                }
            }
        }
        // epilogue: bias + fp32 store to ns
        #pragma unroll
        for (int nf = 0; nf < 2; nf++) {
            const int c0 = n0 + 8 * nf + 2 * tg;
            const float2 bv = *reinterpret_cast<const float2*>(b2 + c0);
            #pragma unroll
            for (int mi = 0; mi < 4; mi++) {
                const int r0 = 16 * mi + g;
                float2 o0, o1;
                o0.x = d[mi][nf][0] + bv.x;
                o0.y = d[mi][nf][1] + bv.y;
                o1.x = d[mi][nf][2] + bv.x;
                o1.y = d[mi][nf][3] + bv.y;
                *reinterpret_cast<float2*>(ns + r0 * NSY + c0)       = o0;
                *reinterpret_cast<float2*>(ns + (r0 + 8) * NSY + c0) = o1;
            }
        }
    }
    __syncthreads();

    // ================= GAT1, GAT2 (+fused coord projection) =================
    // wb aliases the (now dead) h planes: 16 warps * 612 floats = 9792 <= 16896.
    float* wb = reinterpret_cast<float*>(hh);
    gat_layer<false>(ns, wb, adjs, adj1, Wg1, bg1, Wc, bc, nullptr, tid);
    gat_layer<true >(ns, wb, adjs, adj2, Wg2, bg2, Wc, bc,
                     out + (size_t)tok0 * NN * 2, tid);
}

extern "C" void kernel_launch(void* const* d_in, const int* in_sizes, int n_in,
                              void* d_out, int out_size) {
    const float* x    = (const float*)d_in[0];
    const float* W1   = (const float*)d_in[1];
    const float* b1   = (const float*)d_in[2];
    const float* W2   = (const float*)d_in[3];
    const float* b2   = (const float*)d_in[4];
    const float* adj1 = (const float*)d_in[5];
    const float* Wg1  = (const float*)d_in[6];
    const float* bg1  = (const float*)d_in[7];
    const float* adj2 = (const float*)d_in[8];
    const float* Wg2  = (const float*)d_in[9];
    const float* bg2  = (const float*)d_in[10];
    const float* Wc   = (const float*)d_in[11];
    const float* bc   = (const float*)d_in[12];
    float* out = (float*)d_out;

    const size_t smem = SMEM_FLOATS * sizeof(float);
    cudaFuncSetAttribute((const void*)biogat_kernel,
                         cudaFuncAttributeMaxDynamicSharedMemorySize, (int)smem);
    biogat_kernel<<<NCTA, THREADS, smem>>>(x, W1, b1, W2, b2,
                                           adj1, Wg1, bg1,
                                           adj2, Wg2, bg2,
                                           Wc, bc, out);
}

// round 14
// speedup vs baseline: 1.7288x; 1.1514x over previous
#include <cuda_runtime.h>
#include <math.h>
#include <stdint.h>

#define THREADS 512
#define TT      64
#define N_TOK   65536
#define NCTA    (N_TOK / TT)     // 1024
#define DM      128
#define HID     256
#define NN      17
#define NF      32
#define ND      544              // 17*32

#define NSY  548                 // ns row stride (floats)
#define HPLW 132                 // h-plane row stride (u32 words)
#define XPW  68                  // x-plane row stride (u32 words)

// ---- smem layout (floats) ----
// ns [64][548] | wb region (16 warps * 1224; h hi/lo planes alias its head) | adj
#define OFF_NS   0
#define SZ_NS    (TT * NSY)            // 35072
#define OFF_WB   (OFF_NS + SZ_NS)      // 35072
#define SZ_WB    (16 * 1224)           // 19584  (>= 2*TT*HPLW = 16896 for h planes)
#define OFF_ADJ  (OFF_WB + SZ_WB)      // 54656
#define SZ_ADJ   292
#define SMEM_FLOATS (OFF_ADJ + SZ_ADJ) // 54948 floats = 219792 B (< 227 KB cap)

// pre-split weights in fragment-packed layout: {hi0, hi1, lo0, lo1} per lane
__device__ uint4 g_w1p[16 * 8 * 2 * 32];    // group = (j*8+kc)*2+fi,  128 KB
__device__ uint4 g_w2p[34 * 16 * 2 * 32];   // group = (j*16+kc)*2+fi, 557 KB

__device__ __forceinline__ float gelu_f(float v) {
    return 0.5f * v * (1.0f + erff(v * 0.7071067811865476f));
}

// split a k-pair (v0 = even k, v1 = odd k) into packed bf16x2 hi and lo words.
__device__ __forceinline__ void pair_split(float v0, float v1, uint32_t& hi, uint32_t& lo) {
    uint32_t h;
    asm("cvt.rn.bf16x2.f32 %0, %1, %2;" : "=r"(h) : "f"(v1), "f"(v0));
    float h0 = __uint_as_float(h << 16);
    float h1 = __uint_as_float(h & 0xffff0000u);
    asm("cvt.rn.bf16x2.f32 %0, %1, %2;" : "=r"(lo) : "f"(v1 - h1), "f"(v0 - h0));
    hi = h;
}

// m16n8k16 bf16 MMA, fp32 accumulate
__device__ __forceinline__ void mma_bf16(float* d, const uint32_t* a, const uint32_t* b) {
    asm volatile(
        "mma.sync.aligned.m16n8k16.row.col.f32.bf16.bf16.f32 "
        "{%0,%1,%2,%3}, {%4,%5,%6,%7}, {%8,%9}, {%0,%1,%2,%3};"
        : "+f"(d[0]), "+f"(d[1]), "+f"(d[2]), "+f"(d[3])
        : "r"(a[0]), "r"(a[1]), "r"(a[2]), "r"(a[3]), "r"(b[0]), "r"(b[1]));
}

// ---------------- prologue: pack W1/W2 into bf16 hi/lo fragment layout ----------------
extern "C" __global__ void __launch_bounds__(256)
split_weights_kernel(const float* __restrict__ W1, const float* __restrict__ W2)
{
    const int idx  = blockIdx.x * 256 + threadIdx.x;   // 168*256 = 43008
    const int grp  = idx >> 5;
    const int lane = idx & 31;
    const int g    = lane >> 2;
    const int tg   = lane & 3;
    if (grp < 256) {                                   // W1: j(16) kc(8) fi(2)
        const int fi = grp & 1, kc = (grp >> 1) & 7, j = grp >> 4;
        const int col = 16 * j + 8 * fi + g;
        const int k0  = 16 * kc + 2 * tg;
        uint32_t h0, l0, h1, l1;
        pair_split(W1[k0 * HID + col],       W1[(k0 + 1) * HID + col], h0, l0);
        pair_split(W1[(k0 + 8) * HID + col], W1[(k0 + 9) * HID + col], h1, l1);
        uint4 v; v.x = h0; v.y = h1; v.z = l0; v.w = l1;
        g_w1p[grp * 32 + lane] = v;
    } else if (grp < 256 + 1088) {                     // W2: j(34) kc(16) fi(2)
        const int g2 = grp - 256;
        const int fi = g2 & 1, kc = (g2 >> 1) & 15, j = g2 >> 5;
        const int col = 16 * j + 8 * fi + g;
        const int k0  = 16 * kc + 2 * tg;
        uint32_t h0, l0, h1, l1;
        pair_split(W2[(size_t)k0 * ND + col],       W2[(size_t)(k0 + 1) * ND + col], h0, l0);
        pair_split(W2[(size_t)(k0 + 8) * ND + col], W2[(size_t)(k0 + 9) * ND + col], h1, l1);
        uint4 v; v.x = h0; v.y = h1; v.z = l0; v.w = l1;
        g_w2p[g2 * 32 + lane] = v;
    }
}

// ---------------- GAT layer: 16 warps, warp owns 4 tokens (2 pairs) ----------------
template<bool FINAL>
__device__ __forceinline__ void gat_layer(
    float* __restrict__ ns, float* __restrict__ buf, float* __restrict__ adjs,
    const float* __restrict__ adjG, const float* __restrict__ WgG,
    const float* __restrict__ bgG,
    const float* __restrict__ Wc, const float* __restrict__ bc,
    float* __restrict__ outp, int tid)
{
    const int lane = tid & 31;
    const int wid  = tid >> 5;

    if (tid < NN) {
        float r[NN];
        float mx = -3.0e38f;
        #pragma unroll
        for (int j = 0; j < NN; j++) { r[j] = adjG[tid * NN + j]; mx = fmaxf(mx, r[j]); }
        float s = 0.0f;
        #pragma unroll
        for (int j = 0; j < NN; j++) { r[j] = expf(r[j] - mx); s += r[j]; }
        float inv = 1.0f / s;
        #pragma unroll
        for (int j = 0; j < NN; j++) adjs[tid * NN + j] = r[j] * inv;
    }

    float wg[NF];
    #pragma unroll
    for (int g = 0; g < NF; g++) wg[g] = WgG[g * NF + lane];
    const float bgv = bgG[lane];
    float wc0 = 0.0f, wc1 = 0.0f, bc0 = 0.0f, bc1 = 0.0f;
    if (FINAL) { wc0 = Wc[2 * lane]; wc1 = Wc[2 * lane + 1]; bc0 = bc[0]; bc1 = bc[1]; }

    __syncthreads();   // adjs ready; orders vs previous phase

    float* wb = buf + wid * 1224;   // per-warp: 2 tokens x (17*36=612); fits SZ_WB exactly

    // linear + residual (+ optional coord projection) for one token
    auto do_lin = [&](const float (&nr)[NN], const float* wbt, int t) {
        #pragma unroll 1
        for (int i = 0; i < NN; i++) {
            float o = bgv;
            const float4* mp = reinterpret_cast<const float4*>(wbt + i * 36);
            #pragma unroll
            for (int q = 0; q < 8; q++) {
                float4 mv = mp[q];
                o += mv.x * wg[4*q] + mv.y * wg[4*q+1] + mv.z * wg[4*q+2] + mv.w * wg[4*q+3];
            }
            const float val = gelu_f(o) + nr[i];
            if (FINAL) {
                float s0 = val * wc0;
                float s1 = val * wc1;
                #pragma unroll
                for (int off = 16; off; off >>= 1) {
                    s0 += __shfl_xor_sync(0xffffffffu, s0, off);
                    s1 += __shfl_xor_sync(0xffffffffu, s1, off);
                }
                if (lane == 0) {
                    float2 r2;
                    r2.x = s0 + bc0;
                    r2.y = s1 + bc1;
                    *reinterpret_cast<float2*>(outp + (t * NN + i) * 2) = r2;
                }
            } else {
                ns[t * NSY + i * NF + lane] = val;
            }
        }
    };

    #pragma unroll 1
    for (int tp = 0; tp < 2; tp++) {
        const int t0 = wid * 4 + tp * 2;
        const float* nt0 = ns + t0 * NSY;
        const float* nt1 = nt0 + NSY;

        float nr0[NN], nr1[NN];
        #pragma unroll
        for (int j = 0; j < NN; j++) { nr0[j] = nt0[j * NF + lane]; nr1[j] = nt1[j * NF + lane]; }

        // mixed for BOTH tokens per adj-row sweep: each a_ij uniform-load once per pair
        #pragma unroll 1
        for (int i = 0; i < NN; i++) {
            const float* ar = adjs + i * NN;
            float m0 = 0.0f, m1 = 0.0f;
            #pragma unroll
            for (int j = 0; j < NN; j++) {
                const float a = ar[j];
                m0 += a * nr0[j];
                m1 += a * nr1[j];
            }
            wb[i * 36 + lane]       = m0;
            wb[612 + i * 36 + lane] = m1;
        }
        __syncwarp();

        do_lin(nr0, wb,       t0);
        do_lin(nr1, wb + 612, t0 + 1);
        __syncwarp();
    }
    __syncthreads();
}

// ---------------- fused main kernel ----------------
extern "C" __global__ void __launch_bounds__(THREADS, 1)
biogat_kernel(const float* __restrict__ x,
              const float* __restrict__ b1,  const float* __restrict__ b2,
              const float* __restrict__ adj1, const float* __restrict__ Wg1, const float* __restrict__ bg1,
              const float* __restrict__ adj2, const float* __restrict__ Wg2, const float* __restrict__ bg2,
              const float* __restrict__ Wc,  const float* __restrict__ bc,
              float* __restrict__ out)
{
    extern __shared__ float sh[];
    float*    ns   = sh + OFF_NS;
    float*    wbr  = sh + OFF_WB;
    float*    adjs = sh + OFF_ADJ;

    // h hi/lo planes alias the head of the wb region (dead once GAT starts)
    uint32_t* hh = reinterpret_cast<uint32_t*>(wbr);
    uint32_t* hl = hh + TT * HPLW;

    // x planes alias the ns region (dead before phase 2 writes ns)
    uint32_t* xh = reinterpret_cast<uint32_t*>(sh + OFF_NS);
    uint32_t* xl = xh + TT * XPW;

    const int tid  = threadIdx.x;
    const int w    = tid >> 5;    // 0..15
    const int lane = tid & 31;
    const int g    = lane >> 2;
    const int tg   = lane & 3;
    const int tok0 = blockIdx.x * TT;

    // ---- stage + split x ONCE into fragment-permuted bf16 hi/lo planes ----
    {
        const float2* xg = reinterpret_cast<const float2*>(x + (size_t)tok0 * DM);
        #pragma unroll
        for (int it = 0; it < (TT * 64) / THREADS; it++) {
            const int p = tid + it * THREADS;
            const int r = p >> 6, q = p & 63;
            float2 v = xg[p];
            uint32_t hi, lo; pair_split(v.x, v.y, hi, lo);
            const int slot = (q >> 3) * 8 + 2 * (q & 3) + ((q & 7) >> 2);
            xh[r * XPW + slot] = hi;
            xl[r * XPW + slot] = lo;
        }
    }
    __syncthreads();

    // ================= phase 1: h = gelu(x @ W1 + b1) =================
    {
        const int n0 = 16 * w;
        float d[4][2][4] = {};
        #pragma unroll 1
        for (int kc = 0; kc < 8; kc++) {
            uint32_t bh[2][2], bl[2][2];
            #pragma unroll
            for (int fi = 0; fi < 2; fi++) {
                uint4 bw = g_w1p[((w * 8 + kc) * 2 + fi) * 32 + lane];  // coalesced LDG.128
                bh[fi][0] = bw.x; bh[fi][1] = bw.y;
                bl[fi][0] = bw.z; bl[fi][1] = bw.w;
            }
            #pragma unroll
            for (int mi = 0; mi < 4; mi++) {
                const int r0 = 16 * mi + g;
                const int base = kc * 8 + 2 * tg;
                uint32_t ah[4], al[4];
                uint2 t0, t1;
                t0 = *reinterpret_cast<const uint2*>(xh + r0 * XPW + base);
                t1 = *reinterpret_cast<const uint2*>(xh + (r0 + 8) * XPW + base);
                ah[0] = t0.x; ah[2] = t0.y; ah[1] = t1.x; ah[3] = t1.y;
                t0 = *reinterpret_cast<const uint2*>(xl + r0 * XPW + base);
                t1 = *reinterpret_cast<const uint2*>(xl + (r0 + 8) * XPW + base);
                al[0] = t0.x; al[2] = t0.y; al[1] = t1.x; al[3] = t1.y;
                #pragma unroll
                for (int fi = 0; fi < 2; fi++) {
                    mma_bf16(d[mi][fi], ah, bh[fi]);
                    mma_bf16(d[mi][fi], al, bh[fi]);
                    mma_bf16(d[mi][fi], ah, bl[fi]);
                }
            }
        }
        // epilogue: bias + gelu + split-pack into h planes
        const float2 bv0 = *reinterpret_cast<const float2*>(b1 + n0 + 2 * tg);
        const float2 bv1 = *reinterpret_cast<const float2*>(b1 + n0 + 8 + 2 * tg);
        #pragma unroll
        for (int mi = 0; mi < 4; mi++) {
            #pragma unroll
            for (int half = 0; half < 2; half++) {
                const int row = 16 * mi + g + 8 * half;
                uint32_t hw0, lw0, hw1, lw1;
                pair_split(gelu_f(d[mi][0][2*half]   + bv0.x),
                           gelu_f(d[mi][0][2*half+1] + bv0.y), hw0, lw0);
                pair_split(gelu_f(d[mi][1][2*half]   + bv1.x),
                           gelu_f(d[mi][1][2*half+1] + bv1.y), hw1, lw1);
                const int widx = row * HPLW + w * 8 + 2 * tg;
                uint2 hv; hv.x = hw0; hv.y = hw1;
                uint2 lv; lv.x = lw0; lv.y = lw1;
                *reinterpret_cast<uint2*>(hh + widx) = hv;
                *reinterpret_cast<uint2*>(hl + widx) = lv;
            }
        }
    }
    __syncthreads();

    // ================= phase 2: nodes = h @ W2 + b2 =================
    #pragma unroll 1
    for (int j = w; j < 34; j += 16) {
        const int n0 = 16 * j;
        float d[4][2][4] = {};
        #pragma unroll 1
        for (int kc = 0; kc < 16; kc++) {
            uint32_t bh[2][2], bl[2][2];
            #pragma unroll
            for (int nf = 0; nf < 2; nf++) {
                uint4 bw = g_w2p[((j * 16 + kc) * 2 + nf) * 32 + lane];  // coalesced LDG.128
                bh[nf][0] = bw.x; bh[nf][1] = bw.y;
                bl[nf][0] = bw.z; bl[nf][1] = bw.w;
            }
            #pragma unroll
            for (int mi = 0; mi < 4; mi++) {
                const int r0 = 16 * mi + g;
                const int base = kc * 8 + 2 * tg;
                uint32_t ah[4], al[4];
                uint2 t0, t1;
                t0 = *reinterpret_cast<const uint2*>(hh + r0 * HPLW + base);
                t1 = *reinterpret_cast<const uint2*>(hh + (r0 + 8) * HPLW + base);
                ah[0] = t0.x; ah[2] = t0.y; ah[1] = t1.x; ah[3] = t1.y;
                t0 = *reinterpret_cast<const uint2*>(hl + r0 * HPLW + base);
                t1 = *reinterpret_cast<const uint2*>(hl + (r0 + 8) * HPLW + base);
                al[0] = t0.x; al[2] = t0.y; al[1] = t1.x; al[3] = t1.y;
                #pragma unroll
                for (int nf = 0; nf < 2; nf++) {
                    mma_bf16(d[mi][nf], ah, bh[nf]);
                    mma_bf16(d[mi][nf], al, bh[nf]);
                    mma_bf16(d[mi][nf], ah, bl[nf]);
                }
            }
        }
        #pragma unroll
        for (int nf = 0; nf < 2; nf++) {
            const int c0 = n0 + 8 * nf + 2 * tg;
            const float2 bv = *reinterpret_cast<const float2*>(b2 + c0);
            #pragma unroll
            for (int mi = 0; mi < 4; mi++) {
                const int r0 = 16 * mi + g;
                float2 o0, o1;
                o0.x = d[mi][nf][0] + bv.x;
                o0.y = d[mi][nf][1] + bv.y;
                o1.x = d[mi][nf][2] + bv.x;
                o1.y = d[mi][nf][3] + bv.y;
                *reinterpret_cast<float2*>(ns + r0 * NSY + c0)       = o0;
                *reinterpret_cast<float2*>(ns + (r0 + 8) * NSY + c0) = o1;
            }
        }
    }
    __syncthreads();

    // ================= GAT1, GAT2 (+fused coord projection) =================
    gat_layer<false>(ns, wbr, adjs, adj1, Wg1, bg1, Wc, bc, nullptr, tid);
    gat_layer<true >(ns, wbr, adjs, adj2, Wg2, bg2, Wc, bc,
                     out + (size_t)tok0 * NN * 2, tid);
}

extern "C" void kernel_launch(void* const* d_in, const int* in_sizes, int n_in,
                              void* d_out, int out_size) {
    const float* x    = (const float*)d_in[0];
    const float* W1   = (const float*)d_in[1];
    const float* b1   = (const float*)d_in[2];
    const float* W2   = (const float*)d_in[3];
    const float* b2   = (const float*)d_in[4];
    const float* adj1 = (const float*)d_in[5];
    const float* Wg1  = (const float*)d_in[6];
    const float* bg1  = (const float*)d_in[7];
    const float* adj2 = (const float*)d_in[8];
    const float* Wg2  = (const float*)d_in[9];
    const float* bg2  = (const float*)d_in[10];
    const float* Wc   = (const float*)d_in[11];
    const float* bc   = (const float*)d_in[12];
    float* out = (float*)d_out;

    split_weights_kernel<<<168, 256>>>(W1, W2);

    const size_t smem = SMEM_FLOATS * sizeof(float);
    cudaFuncSetAttribute((const void*)biogat_kernel,
                         cudaFuncAttributeMaxDynamicSharedMemorySize, (int)smem);
    biogat_kernel<<<NCTA, THREADS, smem>>>(x, b1, b2,
                                           adj1, Wg1, bg1,
                                           adj2, Wg2, bg2,
                                           Wc, bc, out);
}

// round 15
// speedup vs baseline: 2.0659x; 1.1950x over previous
#include <cuda_runtime.h>
#include <math.h>
#include <stdint.h>

#define THREADS 512
#define TT      64
#define N_TOK   65536
#define NCTA    (N_TOK / TT)     // 1024
#define DM      128
#define HID     256
#define NN      17
#define NF      32
#define ND      544              // 17*32

#define NSY  548                 // ns row stride (floats)
#define HPLW 132                 // h-plane row stride (u32 words)
#define XPW  68                  // x-plane row stride (u32 words)
#define MPLW 18                  // mixed-plane row stride (u32 words; 16 + 2 pad)

// ---- smem layout (floats) ----
// ns [64][548] | plane region (19584: h hi/lo planes, later mixed hi/lo planes) | adj
#define OFF_NS   0
#define SZ_NS    (TT * NSY)            // 35072
#define OFF_WB   (OFF_NS + SZ_NS)      // 35072
#define SZ_WB    19584                 // >= 2*64*132 (h) and == 2*544*18 (mixed)
#define OFF_ADJ  (OFF_WB + SZ_WB)      // 54656
#define SZ_ADJ   292
#define SMEM_FLOATS (OFF_ADJ + SZ_ADJ) // 54948 floats = 219792 B

// pre-split weights in fragment-packed layout: {hi0, hi1, lo0, lo1} per lane
__device__ uint4 g_w1p[16 * 8 * 2 * 32];    // group = (j*8+kc)*2+fi
__device__ uint4 g_w2p[34 * 16 * 2 * 32];   // group = (j*16+kc)*2+fi

__device__ __forceinline__ float gelu_f(float v) {
    return 0.5f * v * (1.0f + erff(v * 0.7071067811865476f));
}

// split a k-pair (v0 = even k, v1 = odd k) into packed bf16x2 hi and lo words.
__device__ __forceinline__ void pair_split(float v0, float v1, uint32_t& hi, uint32_t& lo) {
    uint32_t h;
    asm("cvt.rn.bf16x2.f32 %0, %1, %2;" : "=r"(h) : "f"(v1), "f"(v0));
    float h0 = __uint_as_float(h << 16);
    float h1 = __uint_as_float(h & 0xffff0000u);
    asm("cvt.rn.bf16x2.f32 %0, %1, %2;" : "=r"(lo) : "f"(v1 - h1), "f"(v0 - h0));
    hi = h;
}

// m16n8k16 bf16 MMA, fp32 accumulate
__device__ __forceinline__ void mma_bf16(float* d, const uint32_t* a, const uint32_t* b) {
    asm volatile(
        "mma.sync.aligned.m16n8k16.row.col.f32.bf16.bf16.f32 "
        "{%0,%1,%2,%3}, {%4,%5,%6,%7}, {%8,%9}, {%0,%1,%2,%3};"
        : "+f"(d[0]), "+f"(d[1]), "+f"(d[2]), "+f"(d[3])
        : "r"(a[0]), "r"(a[1]), "r"(a[2]), "r"(a[3]), "r"(b[0]), "r"(b[1]));
}

// ---------------- prologue: pack W1/W2 into bf16 hi/lo fragment layout ----------------
extern "C" __global__ void __launch_bounds__(256)
split_weights_kernel(const float* __restrict__ W1, const float* __restrict__ W2)
{
    const int idx  = blockIdx.x * 256 + threadIdx.x;   // 168*256 = 43008
    const int grp  = idx >> 5;
    const int lane = idx & 31;
    const int g    = lane >> 2;
    const int tg   = lane & 3;
    if (grp < 256) {                                   // W1: j(16) kc(8) fi(2)
        const int fi = grp & 1, kc = (grp >> 1) & 7, j = grp >> 4;
        const int col = 16 * j + 8 * fi + g;
        const int k0  = 16 * kc + 2 * tg;
        uint32_t h0, l0, h1, l1;
        pair_split(W1[k0 * HID + col],       W1[(k0 + 1) * HID + col], h0, l0);
        pair_split(W1[(k0 + 8) * HID + col], W1[(k0 + 9) * HID + col], h1, l1);
        uint4 v; v.x = h0; v.y = h1; v.z = l0; v.w = l1;
        g_w1p[grp * 32 + lane] = v;
    } else if (grp < 256 + 1088) {                     // W2: j(34) kc(16) fi(2)
        const int g2 = grp - 256;
        const int fi = g2 & 1, kc = (g2 >> 1) & 15, j = g2 >> 5;
        const int col = 16 * j + 8 * fi + g;
        const int k0  = 16 * kc + 2 * tg;
        uint32_t h0, l0, h1, l1;
        pair_split(W2[(size_t)k0 * ND + col],       W2[(size_t)(k0 + 1) * ND + col], h0, l0);
        pair_split(W2[(size_t)(k0 + 8) * ND + col], W2[(size_t)(k0 + 9) * ND + col], h1, l1);
        uint4 v; v.x = h0; v.y = h1; v.z = l0; v.w = l1;
        g_w2p[g2 * 32 + lane] = v;
    }
}

// ---------------- GAT layer: mixed (FFMA) + linear (bf16x3 MMA GEMM) ----------------
// Per 32-token half: mixed -> split planes [544 x 32]; GEMM @ Wg[32x32]; epilogue
// fuses bias+gelu+residual (and coord projection when FINAL).
template<bool FINAL>
__device__ __forceinline__ void gat_layer(
    float* __restrict__ ns, uint32_t* __restrict__ mh, uint32_t* __restrict__ ml,
    float* __restrict__ adjs,
    const float* __restrict__ adjG, const float* __restrict__ WgG,
    const float* __restrict__ bgG,
    const float* __restrict__ Wc, const float* __restrict__ bc,
    float* __restrict__ outp, int tid)
{
    const int lane = tid & 31;
    const int wid  = tid >> 5;
    const int g    = lane >> 2;
    const int tg   = lane & 3;

    if (tid < NN) {
        float r[NN];
        float mx = -3.0e38f;
        #pragma unroll
        for (int j = 0; j < NN; j++) { r[j] = adjG[tid * NN + j]; mx = fmaxf(mx, r[j]); }
        float s = 0.0f;
        #pragma unroll
        for (int j = 0; j < NN; j++) { r[j] = expf(r[j] - mx); s += r[j]; }
        float inv = 1.0f / s;
        #pragma unroll
        for (int j = 0; j < NN; j++) adjs[tid * NN + j] = r[j] * inv;
    }
    __syncthreads();   // adjs ready; also orders previous phase's ns writes

    // mixed-plane slot for this lane's feature pair p = lane>>1
    const int pp   = lane >> 1;
    const int slot = (pp >> 3) * 8 + 2 * (pp & 3) + ((pp & 7) >> 2);

    #pragma unroll 1
    for (int half = 0; half < 2; half++) {
        // ---- mixed: warp's 2 tokens -> split bf16 planes ----
        {
            const int tA  = half * 32 + wid * 2;
            const float* ntA = ns + tA * NSY;
            const float* ntB = ntA + NSY;
            float nrA[NN], nrB[NN];
            #pragma unroll
            for (int j = 0; j < NN; j++) {
                nrA[j] = ntA[j * NF + lane];
                nrB[j] = ntB[j * NF + lane];
            }
            const int rA = (wid * 2) * NN;        // local plane row base, token A
            #pragma unroll 1
            for (int i = 0; i < NN; i++) {
                const float* ar = adjs + i * NN;
                float mA = 0.0f, mB = 0.0f;
                #pragma unroll
                for (int j = 0; j < NN; j++) {
                    const float a = ar[j];
                    mA += a * nrA[j];
                    mB += a * nrB[j];
                }
                const float vA = __shfl_xor_sync(0xffffffffu, mA, 1);
                const float vB = __shfl_xor_sync(0xffffffffu, mB, 1);
                uint32_t hi, lo;
                int row;
                if (lane & 1) { pair_split(vB, mB, hi, lo); row = rA + NN + i; }
                else          { pair_split(mA, vA, hi, lo); row = rA + i; }
                mh[row * MPLW + slot] = hi;
                ml[row * MPLW + slot] = lo;
            }
        }
        __syncthreads();   // planes complete before cross-warp GEMM reads

        // ---- GEMM [544 x 32] @ Wg[32 x 32] (bf16x3) + fused epilogue ----
        {
            // B-frags from Wg (row-major [f_in][f_out]): kc(2) x nf(4)
            uint32_t bh[2][4][2], bl[2][4][2];
            #pragma unroll
            for (int kc = 0; kc < 2; kc++)
                #pragma unroll
                for (int nf = 0; nf < 4; nf++) {
                    const int col = 8 * nf + g;
                    const int k0  = 16 * kc + 2 * tg;
                    pair_split(WgG[k0 * NF + col],       WgG[(k0 + 1) * NF + col],
                               bh[kc][nf][0], bl[kc][nf][0]);
                    pair_split(WgG[(k0 + 8) * NF + col], WgG[(k0 + 9) * NF + col],
                               bh[kc][nf][1], bl[kc][nf][1]);
                }
            float bgr[4][2];
            #pragma unroll
            for (int nf = 0; nf < 4; nf++) {
                bgr[nf][0] = bgG[8 * nf + 2 * tg];
                bgr[nf][1] = bgG[8 * nf + 2 * tg + 1];
            }
            float wcr[4][2][2], bc0 = 0.0f, bc1 = 0.0f;
            if (FINAL) {
                #pragma unroll
                for (int nf = 0; nf < 4; nf++)
                    #pragma unroll
                    for (int jj = 0; jj < 2; jj++) {
                        wcr[nf][jj][0] = Wc[(8 * nf + 2 * tg + jj) * 2];
                        wcr[nf][jj][1] = Wc[(8 * nf + 2 * tg + jj) * 2 + 1];
                    }
                bc0 = bc[0]; bc1 = bc[1];
            }

            #pragma unroll 1
            for (int mi = wid; mi < 34; mi += 16) {
                float d[4][4] = {};
                const int r0 = 16 * mi + g;
                #pragma unroll
                for (int kc = 0; kc < 2; kc++) {
                    const int base = kc * 8 + 2 * tg;
                    uint32_t ah[4], al[4];
                    uint2 q0, q1;
                    q0 = *reinterpret_cast<const uint2*>(mh + r0 * MPLW + base);
                    q1 = *reinterpret_cast<const uint2*>(mh + (r0 + 8) * MPLW + base);
                    ah[0] = q0.x; ah[2] = q0.y; ah[1] = q1.x; ah[3] = q1.y;
                    q0 = *reinterpret_cast<const uint2*>(ml + r0 * MPLW + base);
                    q1 = *reinterpret_cast<const uint2*>(ml + (r0 + 8) * MPLW + base);
                    al[0] = q0.x; al[2] = q0.y; al[1] = q1.x; al[3] = q1.y;
                    #pragma unroll
                    for (int nf = 0; nf < 4; nf++) {
                        mma_bf16(d[nf], ah, bh[kc][nf]);
                        mma_bf16(d[nf], al, bh[kc][nf]);
                        mma_bf16(d[nf], ah, bl[kc][nf]);
                    }
                }
                // epilogue: rows rg0 (d[.][0..1]) and rg0+8 (d[.][2..3])
                const int rg0 = half * 544 + r0;
                const int rg1 = rg0 + 8;
                const int t0i = rg0 / NN, i0 = rg0 - t0i * NN;
                const int t1i = rg1 / NN, i1 = rg1 - t1i * NN;
                float* p0base = ns + t0i * NSY + i0 * NF;
                float* p1base = ns + t1i * NSY + i1 * NF;
                if (!FINAL) {
                    #pragma unroll
                    for (int nf = 0; nf < 4; nf++) {
                        const int c0 = 8 * nf + 2 * tg;
                        float2 rv0 = *reinterpret_cast<float2*>(p0base + c0);
                        float2 rv1 = *reinterpret_cast<float2*>(p1base + c0);
                        float2 o0, o1;
                        o0.x = gelu_f(d[nf][0] + bgr[nf][0]) + rv0.x;
                        o0.y = gelu_f(d[nf][1] + bgr[nf][1]) + rv0.y;
                        o1.x = gelu_f(d[nf][2] + bgr[nf][0]) + rv1.x;
                        o1.y = gelu_f(d[nf][3] + bgr[nf][1]) + rv1.y;
                        *reinterpret_cast<float2*>(p0base + c0) = o0;
                        *reinterpret_cast<float2*>(p1base + c0) = o1;
                    }
                } else {
                    float s00 = 0.0f, s01 = 0.0f, s10 = 0.0f, s11 = 0.0f;
                    #pragma unroll
                    for (int nf = 0; nf < 4; nf++) {
                        const int c0 = 8 * nf + 2 * tg;
                        float2 rv0 = *reinterpret_cast<float2*>(p0base + c0);
                        float2 rv1 = *reinterpret_cast<float2*>(p1base + c0);
                        const float v0 = gelu_f(d[nf][0] + bgr[nf][0]) + rv0.x;
                        const float v1 = gelu_f(d[nf][1] + bgr[nf][1]) + rv0.y;
                        const float v2 = gelu_f(d[nf][2] + bgr[nf][0]) + rv1.x;
                        const float v3 = gelu_f(d[nf][3] + bgr[nf][1]) + rv1.y;
                        s00 += v0 * wcr[nf][0][0] + v1 * wcr[nf][1][0];
                        s01 += v0 * wcr[nf][0][1] + v1 * wcr[nf][1][1];
                        s10 += v2 * wcr[nf][0][0] + v3 * wcr[nf][1][0];
                        s11 += v2 * wcr[nf][0][1] + v3 * wcr[nf][1][1];
                    }
                    // reduce over tg (lane bits 0-1) within each quad
                    #pragma unroll
                    for (int off = 1; off <= 2; off <<= 1) {
                        s00 += __shfl_xor_sync(0xffffffffu, s00, off);
                        s01 += __shfl_xor_sync(0xffffffffu, s01, off);
                        s10 += __shfl_xor_sync(0xffffffffu, s10, off);
                        s11 += __shfl_xor_sync(0xffffffffu, s11, off);
                    }
                    if (tg == 0) {
                        float2 o0; o0.x = s00 + bc0; o0.y = s01 + bc1;
                        float2 o1; o1.x = s10 + bc0; o1.y = s11 + bc1;
                        *reinterpret_cast<float2*>(outp + t0i * (NN * 2) + i0 * 2) = o0;
                        *reinterpret_cast<float2*>(outp + t1i * (NN * 2) + i1 * 2) = o1;
                    }
                }
            }
        }
        __syncthreads();   // all GEMM reads done before next half overwrites planes
    }
}

// ---------------- fused main kernel ----------------
extern "C" __global__ void __launch_bounds__(THREADS, 1)
biogat_kernel(const float* __restrict__ x,
              const float* __restrict__ b1,  const float* __restrict__ b2,
              const float* __restrict__ adj1, const float* __restrict__ Wg1, const float* __restrict__ bg1,
              const float* __restrict__ adj2, const float* __restrict__ Wg2, const float* __restrict__ bg2,
              const float* __restrict__ Wc,  const float* __restrict__ bc,
              float* __restrict__ out)
{
    extern __shared__ float sh[];
    float*    ns   = sh + OFF_NS;
    float*    wbr  = sh + OFF_WB;
    float*    adjs = sh + OFF_ADJ;

    // h hi/lo planes alias the head of the plane region (dead once GAT starts)
    uint32_t* hh = reinterpret_cast<uint32_t*>(wbr);
    uint32_t* hl = hh + TT * HPLW;
    // mixed hi/lo planes alias the same region during GAT (544*18 each)
    uint32_t* mh = reinterpret_cast<uint32_t*>(wbr);
    uint32_t* ml = mh + 544 * MPLW;

    // x planes alias the ns region (dead before phase 2 writes ns)
    uint32_t* xh = reinterpret_cast<uint32_t*>(sh + OFF_NS);
    uint32_t* xl = xh + TT * XPW;

    const int tid  = threadIdx.x;
    const int w    = tid >> 5;    // 0..15
    const int lane = tid & 31;
    const int g    = lane >> 2;
    const int tg   = lane & 3;
    const int tok0 = blockIdx.x * TT;

    // ---- stage + split x ONCE into fragment-permuted bf16 hi/lo planes ----
    {
        const float2* xg = reinterpret_cast<const float2*>(x + (size_t)tok0 * DM);
        #pragma unroll
        for (int it = 0; it < (TT * 64) / THREADS; it++) {
            const int p = tid + it * THREADS;
            const int r = p >> 6, q = p & 63;
            float2 v = xg[p];
            uint32_t hi, lo; pair_split(v.x, v.y, hi, lo);
            const int slot = (q >> 3) * 8 + 2 * (q & 3) + ((q & 7) >> 2);
            xh[r * XPW + slot] = hi;
            xl[r * XPW + slot] = lo;
        }
    }
    __syncthreads();

    // ================= phase 1: h = gelu(x @ W1 + b1) =================
    {
        const int n0 = 16 * w;
        float d[4][2][4] = {};
        #pragma unroll 1
        for (int kc = 0; kc < 8; kc++) {
            uint32_t bh[2][2], bl[2][2];
            #pragma unroll
            for (int fi = 0; fi < 2; fi++) {
                uint4 bw = g_w1p[((w * 8 + kc) * 2 + fi) * 32 + lane];
                bh[fi][0] = bw.x; bh[fi][1] = bw.y;
                bl[fi][0] = bw.z; bl[fi][1] = bw.w;
            }
            #pragma unroll
            for (int mi = 0; mi < 4; mi++) {
                const int r0 = 16 * mi + g;
                const int base = kc * 8 + 2 * tg;
                uint32_t ah[4], al[4];
                uint2 t0, t1;
                t0 = *reinterpret_cast<const uint2*>(xh + r0 * XPW + base);
                t1 = *reinterpret_cast<const uint2*>(xh + (r0 + 8) * XPW + base);
                ah[0] = t0.x; ah[2] = t0.y; ah[1] = t1.x; ah[3] = t1.y;
                t0 = *reinterpret_cast<const uint2*>(xl + r0 * XPW + base);
                t1 = *reinterpret_cast<const uint2*>(xl + (r0 + 8) * XPW + base);
                al[0] = t0.x; al[2] = t0.y; al[1] = t1.x; al[3] = t1.y;
                #pragma unroll
                for (int fi = 0; fi < 2; fi++) {
                    mma_bf16(d[mi][fi], ah, bh[fi]);
                    mma_bf16(d[mi][fi], al, bh[fi]);
                    mma_bf16(d[mi][fi], ah, bl[fi]);
                }
            }
        }
        const float2 bv0 = *reinterpret_cast<const float2*>(b1 + n0 + 2 * tg);
        const float2 bv1 = *reinterpret_cast<const float2*>(b1 + n0 + 8 + 2 * tg);
        #pragma unroll
        for (int mi = 0; mi < 4; mi++) {
            #pragma unroll
            for (int half = 0; half < 2; half++) {
                const int row = 16 * mi + g + 8 * half;
                uint32_t hw0, lw0, hw1, lw1;
                pair_split(gelu_f(d[mi][0][2*half]   + bv0.x),
                           gelu_f(d[mi][0][2*half+1] + bv0.y), hw0, lw0);
                pair_split(gelu_f(d[mi][1][2*half]   + bv1.x),
                           gelu_f(d[mi][1][2*half+1] + bv1.y), hw1, lw1);
                const int widx = row * HPLW + w * 8 + 2 * tg;
                uint2 hv; hv.x = hw0; hv.y = hw1;
                uint2 lv; lv.x = lw0; lv.y = lw1;
                *reinterpret_cast<uint2*>(hh + widx) = hv;
                *reinterpret_cast<uint2*>(hl + widx) = lv;
            }
        }
    }
    __syncthreads();

    // ================= phase 2: nodes = h @ W2 + b2 =================
    #pragma unroll 1
    for (int j = w; j < 34; j += 16) {
        const int n0 = 16 * j;
        float d[4][2][4] = {};
        #pragma unroll 1
        for (int kc = 0; kc < 16; kc++) {
            uint32_t bh[2][2], bl[2][2];
            #pragma unroll
            for (int nf = 0; nf < 2; nf++) {
                uint4 bw = g_w2p[((j * 16 + kc) * 2 + nf) * 32 + lane];
                bh[nf][0] = bw.x; bh[nf][1] = bw.y;
                bl[nf][0] = bw.z; bl[nf][1] = bw.w;
            }
            #pragma unroll
            for (int mi = 0; mi < 4; mi++) {
                const int r0 = 16 * mi + g;
                const int base = kc * 8 + 2 * tg;
                uint32_t ah[4], al[4];
                uint2 t0, t1;
                t0 = *reinterpret_cast<const uint2*>(hh + r0 * HPLW + base);
                t1 = *reinterpret_cast<const uint2*>(hh + (r0 + 8) * HPLW + base);
                ah[0] = t0.x; ah[2] = t0.y; ah[1] = t1.x; ah[3] = t1.y;
                t0 = *reinterpret_cast<const uint2*>(hl + r0 * HPLW + base);
                t1 = *reinterpret_cast<const uint2*>(hl + (r0 + 8) * HPLW + base);
                al[0] = t0.x; al[2] = t0.y; al[1] = t1.x; al[3] = t1.y;
                #pragma unroll
                for (int nf = 0; nf < 2; nf++) {
                    mma_bf16(d[mi][nf], ah, bh[nf]);
                    mma_bf16(d[mi][nf], al, bh[nf]);
                    mma_bf16(d[mi][nf], ah, bl[nf]);
                }
            }
        }
        #pragma unroll
        for (int nf = 0; nf < 2; nf++) {
            const int c0 = n0 + 8 * nf + 2 * tg;
            const float2 bv = *reinterpret_cast<const float2*>(b2 + c0);
            #pragma unroll
            for (int mi = 0; mi < 4; mi++) {
                const int r0 = 16 * mi + g;
                float2 o0, o1;
                o0.x = d[mi][nf][0] + bv.x;
                o0.y = d[mi][nf][1] + bv.y;
                o1.x = d[mi][nf][2] + bv.x;
                o1.y = d[mi][nf][3] + bv.y;
                *reinterpret_cast<float2*>(ns + r0 * NSY + c0)       = o0;
                *reinterpret_cast<float2*>(ns + (r0 + 8) * NSY + c0) = o1;
            }
        }
    }
    __syncthreads();

    // ================= GAT1, GAT2 (+fused coord projection) =================
    gat_layer<false>(ns, mh, ml, adjs, adj1, Wg1, bg1, Wc, bc, nullptr, tid);
    gat_layer<true >(ns, mh, ml, adjs, adj2, Wg2, bg2, Wc, bc,
                     out + (size_t)tok0 * NN * 2, tid);
}

extern "C" void kernel_launch(void* const* d_in, const int* in_sizes, int n_in,
                              void* d_out, int out_size) {
    const float* x    = (const float*)d_in[0];
    const float* W1   = (const float*)d_in[1];
    const float* b1   = (const float*)d_in[2];
    const float* W2   = (const float*)d_in[3];
    const float* b2   = (const float*)d_in[4];
    const float* adj1 = (const float*)d_in[5];
    const float* Wg1  = (const float*)d_in[6];
    const float* bg1  = (const float*)d_in[7];
    const float* adj2 = (const float*)d_in[8];
    const float* Wg2  = (const float*)d_in[9];
    const float* bg2  = (const float*)d_in[10];
    const float* Wc   = (const float*)d_in[11];
    const float* bc   = (const float*)d_in[12];
    float* out = (float*)d_out;

    split_weights_kernel<<<168, 256>>>(W1, W2);

    const size_t smem = SMEM_FLOATS * sizeof(float);
    cudaFuncSetAttribute((const void*)biogat_kernel,
                         cudaFuncAttributeMaxDynamicSharedMemorySize, (int)smem);
    biogat_kernel<<<NCTA, THREADS, smem>>>(x, b1, b2,
                                           adj1, Wg1, bg1,
                                           adj2, Wg2, bg2,
                                           Wc, bc, out);
}